// round 3
// baseline (speedup 1.0000x reference)
#include <cuda_runtime.h>
#include <math_constants.h>

// VectorQuantizer: x (64,1024,256) f32, codebook vectors (256,4096) f32.
// Outputs (flattened f32): [0,N*D) quantized_st; [N*D] dict_loss; [N*D+1]
// commitment_loss; [N*D+2, +N) indices as float.
//
// Key correctness requirement: argmin must match the reference BIT-EXACTLY.
// Reference score: s_k = fl( fl(A - 2*B_k) + C_k ), A = fl-sum of x^2 per row
// (XLA GPU warp row-reduce order), rounded at ulp(~256). We replicate A's
// exact summation order and the rounding chain; B (fp32 dot, any order) and
// C (fp64->fp32) errors are far below the rounding grain.

#define DDIM 256
#define KDIM 4096
#define MAXN 65536
#define BM 32
#define BN 128
#define BK 32
#define NTHREADS 256

__device__ float  g_v2[KDIM];      // C_k
__device__ float  g_A[MAXN];       // A_n, XLA-order fp32 row sums of x^2
__device__ int    g_idx_buf[MAXN];
__device__ double g_partials[256];

// ---------------------------------------------------------------------------
// Kernel A1: C_k = ||v_k||^2 (fp64 accumulate -> fp32), zero loss partials
// ---------------------------------------------------------------------------
__global__ void vq_prep(const float* __restrict__ vec) {
    int k = blockIdx.x * blockDim.x + threadIdx.x;
    if (k < KDIM) {
        double s = 0.0;
        #pragma unroll 8
        for (int d = 0; d < DDIM; ++d) {
            float v = vec[(size_t)d * KDIM + k];
            s += (double)v * (double)v;
        }
        g_v2[k] = (float)s;
    }
    if (blockIdx.x == 0 && threadIdx.x < 256) g_partials[threadIdx.x] = 0.0;
}

// ---------------------------------------------------------------------------
// Kernel A2: A_n = (x_n^2).sum  -- emulate XLA:GPU row reduction exactly.
// One warp per row. Lane t: acc = (((0 + x_t^2) + x_{t+32}^2) + ...) over 8
// strided elems (mul and add as SEPARATE rounded ops, no fma). Then
// shfl_down tree 16,8,4,2,1 with acc = acc + down.
// ---------------------------------------------------------------------------
__global__ __launch_bounds__(256) void vq_rownorm(const float* __restrict__ x) {
    int warp = threadIdx.x >> 5;
    int lane = threadIdx.x & 31;
    int row  = blockIdx.x * 8 + warp;
    const float* xr = x + (size_t)row * DDIM;

    float acc = 0.0f;
    #pragma unroll
    for (int i = 0; i < 8; ++i) {
        float v  = xr[lane + 32 * i];
        float sq = __fmul_rn(v, v);          // keep mul/add separate (no FMA)
        acc = __fadd_rn(acc, sq);
    }
    #pragma unroll
    for (int off = 16; off > 0; off >>= 1) {
        float d = __shfl_down_sync(0xffffffffu, acc, off);
        acc = __fadd_rn(acc, d);
    }
    if (lane == 0) g_A[row] = acc;
}

// ---------------------------------------------------------------------------
// Kernel B: fused fp32 distance GEMM + quantized argmin.
//   block: 256 threads = 32 (tx: col groups) x 8 (ty: row groups)
//   each thread: 4 rows x 4 cols microtile; x tile in smem, v streamed.
// ---------------------------------------------------------------------------
__global__ __launch_bounds__(NTHREADS) void vq_argmin(
        const float* __restrict__ x, const float* __restrict__ vec,
        float* __restrict__ out_idx, int write_idx) {
    __shared__ float xs[DDIM][BM];   // 32 KB, transposed: xs[d][r]
    __shared__ float vs[BK][BN];     // 16 KB

    const int t  = threadIdx.x;
    const int tx = t & 31;
    const int ty = t >> 5;
    const int row0 = blockIdx.x * BM;

    #pragma unroll
    for (int i = t; i < BM * DDIM / 4; i += NTHREADS) {
        int r  = i >> 6;
        int c4 = i & 63;
        float4 v4 = *(const float4*)(x + (size_t)(row0 + r) * DDIM + c4 * 4);
        xs[c4 * 4 + 0][r] = v4.x;
        xs[c4 * 4 + 1][r] = v4.y;
        xs[c4 * 4 + 2][r] = v4.z;
        xs[c4 * 4 + 3][r] = v4.w;
    }

    float rowA[4];
    #pragma unroll
    for (int i = 0; i < 4; ++i) rowA[i] = g_A[row0 + ty * 4 + i];

    float best[4];
    int   bidx[4];
    #pragma unroll
    for (int i = 0; i < 4; ++i) { best[i] = CUDART_INF_F; bidx[i] = 0; }

    float4 rv[4];
    #pragma unroll
    for (int j = 0; j < 4; ++j)
        rv[j] = *(const float4*)(vec + (size_t)(ty * 4 + j) * KDIM + tx * 4);

    for (int kt = 0; kt < KDIM / BN; ++kt) {
        float acc[4][4];
        #pragma unroll
        for (int i = 0; i < 4; ++i)
            #pragma unroll
            for (int j = 0; j < 4; ++j) acc[i][j] = 0.0f;

        for (int c = 0; c < DDIM / BK; ++c) {
            __syncthreads();
            #pragma unroll
            for (int j = 0; j < 4; ++j)
                *(float4*)&vs[ty * 4 + j][tx * 4] = rv[j];
            __syncthreads();

            int nc = c + 1, nkt = kt;
            if (nc == DDIM / BK) { nc = 0; nkt = kt + 1; }
            if (nkt < KDIM / BN) {
                #pragma unroll
                for (int j = 0; j < 4; ++j)
                    rv[j] = *(const float4*)(vec +
                        (size_t)(nc * BK + ty * 4 + j) * KDIM + nkt * BN + tx * 4);
            }

            #pragma unroll
            for (int dd = 0; dd < BK; ++dd) {
                float4 xv = *(const float4*)&xs[c * BK + dd][ty * 4];
                float4 vv = *(const float4*)&vs[dd][tx * 4];
                acc[0][0] += xv.x * vv.x; acc[0][1] += xv.x * vv.y;
                acc[0][2] += xv.x * vv.z; acc[0][3] += xv.x * vv.w;
                acc[1][0] += xv.y * vv.x; acc[1][1] += xv.y * vv.y;
                acc[1][2] += xv.y * vv.z; acc[1][3] += xv.y * vv.w;
                acc[2][0] += xv.z * vv.x; acc[2][1] += xv.z * vv.y;
                acc[2][2] += xv.z * vv.z; acc[2][3] += xv.z * vv.w;
                acc[3][0] += xv.w * vv.x; acc[3][1] += xv.w * vv.y;
                acc[3][2] += xv.w * vv.z; acc[3][3] += xv.w * vv.w;
            }
        }

        // Quantized scores, exactly as the reference rounds them:
        //   s = fl( fl(A - 2*dot) + C )
        #pragma unroll
        for (int j = 0; j < 4; ++j) {
            int k = kt * BN + tx * 4 + j;
            float c2 = g_v2[k];
            #pragma unroll
            for (int i = 0; i < 4; ++i) {
                float m2 = __fmul_rn(2.0f, acc[i][j]);   // exact
                float t2 = __fsub_rn(rowA[i], m2);       // rounds at ~ulp(256)
                float s  = __fadd_rn(t2, c2);            // rounds at ~ulp(256)
                if (s < best[i]) { best[i] = s; bidx[i] = k; }
            }
        }
    }

    // Cross-lane argmin reduce; ties -> lower index (first occurrence).
    #pragma unroll
    for (int i = 0; i < 4; ++i) {
        float b = best[i];
        int   bi = bidx[i];
        #pragma unroll
        for (int off = 16; off > 0; off >>= 1) {
            float ob = __shfl_down_sync(0xffffffffu, b, off);
            int   oi = __shfl_down_sync(0xffffffffu, bi, off);
            if (ob < b || (ob == b && oi < bi)) { b = ob; bi = oi; }
        }
        if (tx == 0) {
            int row = row0 + ty * 4 + i;
            g_idx_buf[row] = bi;
            if (write_idx) out_idx[row] = (float)bi;
        }
    }
}

// ---------------------------------------------------------------------------
// Kernel C: gather quantized vectors, straight-through output, loss partials
// ---------------------------------------------------------------------------
__global__ void vq_gather(const float* __restrict__ x, const float* __restrict__ vec,
                          float* __restrict__ out) {
    int row = blockIdx.x;
    int d   = threadIdx.x;
    int k   = g_idx_buf[row];
    float q  = vec[(size_t)d * KDIM + k];
    size_t off = (size_t)row * DDIM + d;
    float xv = x[off];
    out[off] = __fadd_rn(xv, __fsub_rn(q, xv));  // x + (q - x), ref's fp ops
    float diff = xv - q;

    __shared__ double sd[256];
    sd[d] = (double)diff * (double)diff;
    __syncthreads();
    #pragma unroll
    for (int s = 128; s > 0; s >>= 1) {
        if (d < s) sd[d] += sd[d + s];
        __syncthreads();
    }
    if (d == 0) atomicAdd(&g_partials[blockIdx.x & 255], sd[0]);
}

// ---------------------------------------------------------------------------
// Kernel D: finalize losses
// ---------------------------------------------------------------------------
__global__ void vq_final(float* __restrict__ out, long long nd, int has_extra) {
    __shared__ double sd[256];
    sd[threadIdx.x] = g_partials[threadIdx.x];
    __syncthreads();
    #pragma unroll
    for (int s = 128; s > 0; s >>= 1) {
        if (threadIdx.x < s) sd[threadIdx.x] += sd[threadIdx.x + s];
        __syncthreads();
    }
    if (threadIdx.x == 0 && has_extra) {
        float l = (float)(sd[0] / (double)nd);
        out[nd]     = l;   // dictionary_loss
        out[nd + 1] = l;   // commitment_loss (same forward value)
    }
}

// ---------------------------------------------------------------------------
extern "C" void kernel_launch(void* const* d_in, const int* in_sizes, int n_in,
                              void* d_out, int out_size) {
    const float* x   = (const float*)d_in[0];
    const float* vec = (const float*)d_in[1];
    float* out = (float*)d_out;

    int n = in_sizes[0] / DDIM;                 // 65536 rows
    long long nd = (long long)n * DDIM;
    int has_extra = ((long long)out_size >= nd + 2 + n) ? 1 : 0;

    vq_prep<<<(KDIM + 255) / 256, 256>>>(vec);
    vq_rownorm<<<n / 8, 256>>>(x);
    vq_argmin<<<n / BM, NTHREADS>>>(x, vec, out + nd + 2, has_extra);
    vq_gather<<<n, DDIM>>>(x, vec, out);
    vq_final<<<1, 256>>>(out, nd, has_extra);
}

// round 5
// speedup vs baseline: 1.3232x; 1.3232x over previous
#include <cuda_runtime.h>
#include <math_constants.h>
#include <cstdint>

// ===========================================================================
// VectorQuantizer: x (64,1024,256) f32, codebook vectors (256,4096) f32.
// Outputs (flattened f32): [0,N*D) quantized_st; [N*D] dict_loss; [N*D+1]
// commitment_loss; [N*D+2, +N) indices as float.
//
// Bit-exact argmin vs reference: s_k = fl( fl(A - 2*B_k) + C_k ), with A the
// XLA-order fp32 row sum of x^2. Distance GEMM done with packed fp32
// fma.rn.f32x2 (2 MAC/instr -> 2x the scalar FFMA roofline on sm_103).
// ===========================================================================

#define DDIM 256
#define KDIM 4096
#define MAXN 65536

__device__ float  g_v2[KDIM];      // C_k = ||v_k||^2
__device__ float  g_A[MAXN];       // A_n (XLA-order row sums)
__device__ int    g_idx_buf[MAXN];
__device__ double g_partials[256];
__device__ float  g_vT[KDIM * DDIM];   // codebook transposed (K,D) for gather

// ---------------------------------------------------------------------------
// f32x2 helpers (family-wide PTX, no 'a' target needed)
// ---------------------------------------------------------------------------
__device__ __forceinline__ unsigned long long pack_dup(float f) {
    unsigned long long u;
    asm("mov.b64 %0, {%1, %1};" : "=l"(u) : "f"(f));
    return u;
}
__device__ __forceinline__ void unpack2(unsigned long long v, float& lo, float& hi) {
    asm("mov.b64 {%0, %1}, %2;" : "=f"(lo), "=f"(hi) : "l"(v));
}
__device__ __forceinline__ void ffma2(unsigned long long& acc,
                                      unsigned long long a, unsigned long long b) {
    asm("fma.rn.f32x2 %0, %1, %2, %0;" : "+l"(acc) : "l"(a), "l"(b));
}

// ---------------------------------------------------------------------------
// Kernel A1: C_k = ||v_k||^2 (fp64 accumulate), zero loss partials
// ---------------------------------------------------------------------------
__global__ void vq_prep(const float* __restrict__ vec) {
    int k = blockIdx.x * blockDim.x + threadIdx.x;
    if (k < KDIM) {
        double s = 0.0;
        #pragma unroll 8
        for (int d = 0; d < DDIM; ++d) {
            float v = vec[(size_t)d * KDIM + k];
            s += (double)v * (double)v;
        }
        g_v2[k] = (float)s;
    }
    if (blockIdx.x == 0 && threadIdx.x < 256) g_partials[threadIdx.x] = 0.0;
}

// ---------------------------------------------------------------------------
// Kernel A2: A_n = (x_n^2).sum  (exact XLA:GPU warp-reduce order — validated)
// ---------------------------------------------------------------------------
__global__ __launch_bounds__(256) void vq_rownorm(const float* __restrict__ x) {
    int warp = threadIdx.x >> 5;
    int lane = threadIdx.x & 31;
    int row  = blockIdx.x * 8 + warp;
    const float* xr = x + (size_t)row * DDIM;
    float acc = 0.0f;
    #pragma unroll
    for (int i = 0; i < 8; ++i) {
        float v = xr[lane + 32 * i];
        acc = __fadd_rn(acc, __fmul_rn(v, v));
    }
    #pragma unroll
    for (int off = 16; off > 0; off >>= 1)
        acc = __fadd_rn(acc, __shfl_down_sync(0xffffffffu, acc, off));
    if (lane == 0) g_A[row] = acc;
}

// ---------------------------------------------------------------------------
// Kernel A3: transpose codebook to (K,D) fp32 for the coalesced gather
// ---------------------------------------------------------------------------
__global__ void vq_transpose(const float* __restrict__ vec) {
    __shared__ float tile[32][33];
    int k0 = blockIdx.x * 32, d0 = blockIdx.y * 32;
    int tx = threadIdx.x, ty = threadIdx.y;       // (32, 8)
    #pragma unroll
    for (int i = 0; i < 4; ++i)
        tile[ty + 8 * i][tx] = vec[(size_t)(d0 + ty + 8 * i) * KDIM + k0 + tx];
    __syncthreads();
    #pragma unroll
    for (int i = 0; i < 4; ++i) {
        int kl = ty + 8 * i;
        g_vT[(size_t)(k0 + kl) * DDIM + d0 + tx] = tile[tx][kl];
    }
}

// ---------------------------------------------------------------------------
// Kernel B: fused distance GEMM (f32x2) + quantized argmin.
//   256 threads; CTA tile 64 rows x 256 cols; microtile 8x8 per thread.
//   tx = t&31 owns col pairs {tx*2 + jp*64}, ty = t>>5 (warp) owns rows ty*8..+7.
//   xs [DDIM][64] resident in smem (64KB); vs [16][256] streamed (16KB).
// ---------------------------------------------------------------------------
#define BM2 64
#define BN2 256
#define BK2 16
#define KT2 (KDIM / BN2)   // 16
#define NC2 (DDIM / BK2)   // 16

__global__ __launch_bounds__(256, 2) void vq_argmin2(
        const float* __restrict__ x, const float* __restrict__ vec,
        float* __restrict__ out_idx, int write_idx) {
    extern __shared__ float sm[];
    float* xs = sm;                 // [DDIM][BM2]
    float* vs = sm + DDIM * BM2;    // [BK2][BN2]

    const int t  = threadIdx.x;
    const int tx = t & 31;
    const int ty = t >> 5;          // warp id; rows ty*8 .. ty*8+7
    const int row0 = blockIdx.x * BM2;

    // Load x tile, transposed into smem (one-time; conflicts acceptable).
    #pragma unroll
    for (int it = 0; it < 16; ++it) {
        int i  = t + it * 256;
        int r  = i >> 6;            // 64 float4 per x row
        int c4 = i & 63;
        float4 v4 = *(const float4*)(x + (size_t)(row0 + r) * DDIM + c4 * 4);
        xs[(c4 * 4 + 0) * BM2 + r] = v4.x;
        xs[(c4 * 4 + 1) * BM2 + r] = v4.y;
        xs[(c4 * 4 + 2) * BM2 + r] = v4.z;
        xs[(c4 * 4 + 3) * BM2 + r] = v4.w;
    }

    float rowA[8];
    #pragma unroll
    for (int i = 0; i < 8; ++i) rowA[i] = g_A[row0 + ty * 8 + i];

    float best[8];
    int   bidx[8];
    #pragma unroll
    for (int i = 0; i < 8; ++i) { best[i] = CUDART_INF_F; bidx[i] = 0; }

    // Prefetch first vs chunk (kt=0, cb=0). 4 float4 per thread.
    float4 rv[4];
    #pragma unroll
    for (int q = 0; q < 4; ++q) {
        int i = t + q * 256;
        int d = i >> 6, k4 = i & 63;     // d: 0..15, 64 float4 per vs row
        rv[q] = *(const float4*)(vec + (size_t)d * KDIM + k4 * 4);
    }

    for (int kt = 0; kt < KT2; ++kt) {
        unsigned long long acc[8][4];
        #pragma unroll
        for (int i = 0; i < 8; ++i)
            #pragma unroll
            for (int jp = 0; jp < 4; ++jp) acc[i][jp] = 0ULL;

        for (int cb = 0; cb < NC2; ++cb) {
            __syncthreads();
            #pragma unroll
            for (int q = 0; q < 4; ++q) {
                int i = t + q * 256;
                int d = i >> 6, k4 = i & 63;
                *(float4*)(vs + d * BN2 + k4 * 4) = rv[q];
            }
            __syncthreads();

            // Prefetch next chunk (overlaps with compute below).
            int ncb = cb + 1, nkt = kt;
            if (ncb == NC2) { ncb = 0; nkt = kt + 1; }
            if (nkt < KT2) {
                #pragma unroll
                for (int q = 0; q < 4; ++q) {
                    int i = t + q * 256;
                    int d = i >> 6, k4 = i & 63;
                    rv[q] = *(const float4*)(vec +
                        (size_t)(ncb * BK2 + d) * KDIM + nkt * BN2 + k4 * 4);
                }
            }

            const float* xp = xs + (cb * BK2) * BM2 + ty * 8;
            #pragma unroll
            for (int dd = 0; dd < BK2; ++dd) {
                // 8 row values (warp-broadcast), duplicated into f32x2 in regs
                float4 xa = *(const float4*)(xp + dd * BM2);
                float4 xb = *(const float4*)(xp + dd * BM2 + 4);
                unsigned long long xd[8];
                xd[0] = pack_dup(xa.x); xd[1] = pack_dup(xa.y);
                xd[2] = pack_dup(xa.z); xd[3] = pack_dup(xa.w);
                xd[4] = pack_dup(xb.x); xd[5] = pack_dup(xb.y);
                xd[6] = pack_dup(xb.z); xd[7] = pack_dup(xb.w);
                // 4 natural col pairs, stride-8B lane addressing (conflict-free)
                unsigned long long vv[4];
                #pragma unroll
                for (int jp = 0; jp < 4; ++jp)
                    vv[jp] = *(const unsigned long long*)(vs + dd * BN2 + tx * 2 + jp * 64);
                #pragma unroll
                for (int i = 0; i < 8; ++i) {
                    ffma2(acc[i][0], xd[i], vv[0]);
                    ffma2(acc[i][1], xd[i], vv[1]);
                    ffma2(acc[i][2], xd[i], vv[2]);
                    ffma2(acc[i][3], xd[i], vv[3]);
                }
            }
        }

        // Epilogue: quantized scores exactly as the reference rounds them,
        // visited in ascending k per thread (strict < == first occurrence).
        #pragma unroll
        for (int jp = 0; jp < 4; ++jp) {
            int kb = kt * BN2 + tx * 2 + jp * 64;
            float c2a = g_v2[kb], c2b = g_v2[kb + 1];
            #pragma unroll
            for (int i = 0; i < 8; ++i) {
                float lo, hi;
                unpack2(acc[i][jp], lo, hi);
                float s0 = __fadd_rn(__fsub_rn(rowA[i], __fmul_rn(2.0f, lo)), c2a);
                if (s0 < best[i]) { best[i] = s0; bidx[i] = kb; }
                float s1 = __fadd_rn(__fsub_rn(rowA[i], __fmul_rn(2.0f, hi)), c2b);
                if (s1 < best[i]) { best[i] = s1; bidx[i] = kb + 1; }
            }
        }
    }

    // Cross-lane argmin reduce within the warp (each warp owns 8 rows).
    #pragma unroll
    for (int i = 0; i < 8; ++i) {
        float b = best[i];
        int   bi = bidx[i];
        #pragma unroll
        for (int off = 16; off > 0; off >>= 1) {
            float ob = __shfl_down_sync(0xffffffffu, b, off);
            int   oi = __shfl_down_sync(0xffffffffu, bi, off);
            if (ob < b || (ob == b && oi < bi)) { b = ob; bi = oi; }
        }
        if (tx == 0) {
            int row = row0 + ty * 8 + i;
            g_idx_buf[row] = bi;
            if (write_idx) out_idx[row] = (float)bi;
        }
    }
}

// ---------------------------------------------------------------------------
// Kernel C: coalesced gather via transposed codebook + loss partials
// ---------------------------------------------------------------------------
__global__ __launch_bounds__(256) void vq_gather2(const float* __restrict__ x,
                                                  float* __restrict__ out) {
    int row  = blockIdx.x * 8 + (threadIdx.x >> 5);
    int lane = threadIdx.x & 31;
    int k = g_idx_buf[row];
    const float4* q4 = (const float4*)(g_vT + (size_t)k * DDIM);
    const float4* x4 = (const float4*)(x + (size_t)row * DDIM);
    float4*       o4 = (float4*)(out + (size_t)row * DDIM);
    double acc = 0.0;
    #pragma unroll
    for (int i = 0; i < 2; ++i) {
        float4 q = q4[lane + 32 * i];
        float4 v = x4[lane + 32 * i];
        float4 o;
        o.x = __fadd_rn(v.x, __fsub_rn(q.x, v.x));
        o.y = __fadd_rn(v.y, __fsub_rn(q.y, v.y));
        o.z = __fadd_rn(v.z, __fsub_rn(q.z, v.z));
        o.w = __fadd_rn(v.w, __fsub_rn(q.w, v.w));
        o4[lane + 32 * i] = o;
        double dx = (double)v.x - (double)q.x, dy = (double)v.y - (double)q.y;
        double dz = (double)v.z - (double)q.z, dw = (double)v.w - (double)q.w;
        acc += dx * dx + dy * dy + dz * dz + dw * dw;
    }
    #pragma unroll
    for (int off = 16; off > 0; off >>= 1)
        acc += __shfl_down_sync(0xffffffffu, acc, off);
    if (lane == 0) atomicAdd(&g_partials[row & 255], acc);
}

// ---------------------------------------------------------------------------
// Kernel D: finalize losses
// ---------------------------------------------------------------------------
__global__ void vq_final(float* __restrict__ out, long long nd, int has_extra) {
    __shared__ double sd[256];
    sd[threadIdx.x] = g_partials[threadIdx.x];
    __syncthreads();
    #pragma unroll
    for (int s = 128; s > 0; s >>= 1) {
        if (threadIdx.x < s) sd[threadIdx.x] += sd[threadIdx.x + s];
        __syncthreads();
    }
    if (threadIdx.x == 0 && has_extra) {
        float l = (float)(sd[0] / (double)nd);
        out[nd]     = l;
        out[nd + 1] = l;
    }
}

// ---------------------------------------------------------------------------
extern "C" void kernel_launch(void* const* d_in, const int* in_sizes, int n_in,
                              void* d_out, int out_size) {
    const float* x   = (const float*)d_in[0];
    const float* vec = (const float*)d_in[1];
    float* out = (float*)d_out;

    int n = in_sizes[0] / DDIM;                 // 65536 rows
    long long nd = (long long)n * DDIM;
    int has_extra = ((long long)out_size >= nd + 2 + n) ? 1 : 0;

    int smem2 = (DDIM * BM2 + BK2 * BN2) * sizeof(float);   // 81920 B
    cudaFuncSetAttribute(vq_argmin2, cudaFuncAttributeMaxDynamicSharedMemorySize, smem2);

    vq_prep<<<(KDIM + 255) / 256, 256>>>(vec);
    vq_rownorm<<<n / 8, 256>>>(x);
    vq_transpose<<<dim3(KDIM / 32, DDIM / 32), dim3(32, 8)>>>(vec);
    vq_argmin2<<<n / BM2, 256, smem2>>>(x, vec, out + nd + 2, has_extra);
    vq_gather2<<<n / 8, 256>>>(x, out);
    vq_final<<<1, 256>>>(out, nd, has_extra);
}

// round 6
// speedup vs baseline: 3.8392x; 2.9014x over previous
#include <cuda_runtime.h>
#include <cuda_bf16.h>
#include <math_constants.h>
#include <cstdint>

// ===========================================================================
// VectorQuantizer: x (64,1024,256) f32, codebook vectors (256,4096) f32.
// Outputs (flattened f32): [0,N*D) quantized_st; [N*D] dict_loss; [N*D+1]
// commitment_loss; [N*D+2, +N) indices as float.
//
// Two-phase argmin:
//   Phase 1: bf16 HMMA (mma.sync m16n8k16, family-wide PTX) computes approx
//            scores s~_k = C_k - 2*dot_bf16; per-row running min + collect all
//            k with s~ <= runmin + TAU (candidate superset, CAP w/ fallback).
//   Phase 2: exact fp32 rescore of candidates with the reference's rounding
//            chain s = fl(fl(A - 2*dot) + C), A = bit-exact XLA row sum.
// ===========================================================================

#define DDIM 256
#define KDIM 4096
#define MAXN 65536
#define CAP  32
#define TAU  2.5e-3f

__device__ float         g_v2[KDIM];          // C_k = ||v_k||^2
__device__ float         g_A[MAXN];           // A_n (XLA-order row sums)
__device__ int           g_idx_buf[MAXN];
__device__ double        g_partials[256];
__device__ float         g_vT[KDIM * DDIM];   // codebook (K,D) fp32
__device__ __nv_bfloat16 g_vTh[KDIM * DDIM];  // codebook (K,D) bf16
__device__ __nv_bfloat16 g_xh[(size_t)MAXN * DDIM];  // x in bf16
__device__ int           g_candcnt[MAXN];
__device__ int           g_cand[MAXN * CAP];

// ---------------------------------------------------------------------------
__device__ __forceinline__ void mma_bf16(float* d, const uint32_t* a,
                                         const uint32_t* b) {
    asm volatile(
        "mma.sync.aligned.m16n8k16.row.col.f32.bf16.bf16.f32 "
        "{%0,%1,%2,%3}, {%4,%5,%6,%7}, {%8,%9}, {%0,%1,%2,%3};"
        : "+f"(d[0]), "+f"(d[1]), "+f"(d[2]), "+f"(d[3])
        : "r"(a[0]), "r"(a[1]), "r"(a[2]), "r"(a[3]), "r"(b[0]), "r"(b[1]));
}

// ---------------------------------------------------------------------------
// Kernel A1: C_k = ||v_k||^2 (fp64 accumulate), zero loss partials
// ---------------------------------------------------------------------------
__global__ void vq_prep(const float* __restrict__ vec) {
    int k = blockIdx.x * blockDim.x + threadIdx.x;
    if (k < KDIM) {
        double s = 0.0;
        #pragma unroll 8
        for (int d = 0; d < DDIM; ++d) {
            float v = vec[(size_t)d * KDIM + k];
            s += (double)v * (double)v;
        }
        g_v2[k] = (float)s;
    }
    if (blockIdx.x == 0 && threadIdx.x < 256) g_partials[threadIdx.x] = 0.0;
}

// ---------------------------------------------------------------------------
// Kernel A2: x -> bf16 (8 elems/thread, packed 16B store)
// ---------------------------------------------------------------------------
__global__ __launch_bounds__(256) void vq_convx(const float* __restrict__ x) {
    size_t i = ((size_t)blockIdx.x * 256 + threadIdx.x) * 8;
    float4 v0 = *(const float4*)(x + i);
    float4 v1 = *(const float4*)(x + i + 4);
    __nv_bfloat16 h[8];
    h[0] = __float2bfloat16_rn(v0.x); h[1] = __float2bfloat16_rn(v0.y);
    h[2] = __float2bfloat16_rn(v0.z); h[3] = __float2bfloat16_rn(v0.w);
    h[4] = __float2bfloat16_rn(v1.x); h[5] = __float2bfloat16_rn(v1.y);
    h[6] = __float2bfloat16_rn(v1.z); h[7] = __float2bfloat16_rn(v1.w);
    *(uint4*)(g_xh + i) = *(const uint4*)h;
}

// ---------------------------------------------------------------------------
// Kernel A3: A_n (exact XLA warp-reduce order, validated) + zero cand counts
// ---------------------------------------------------------------------------
__global__ __launch_bounds__(256) void vq_rownorm(const float* __restrict__ x) {
    int warp = threadIdx.x >> 5;
    int lane = threadIdx.x & 31;
    int row  = blockIdx.x * 8 + warp;
    const float* xr = x + (size_t)row * DDIM;
    float acc = 0.0f;
    #pragma unroll
    for (int i = 0; i < 8; ++i) {
        float v = xr[lane + 32 * i];
        acc = __fadd_rn(acc, __fmul_rn(v, v));
    }
    #pragma unroll
    for (int off = 16; off > 0; off >>= 1)
        acc = __fadd_rn(acc, __shfl_down_sync(0xffffffffu, acc, off));
    if (lane == 0) { g_A[row] = acc; g_candcnt[row] = 0; }
}

// ---------------------------------------------------------------------------
// Kernel A4: transpose codebook to (K,D) fp32 + bf16
// ---------------------------------------------------------------------------
__global__ void vq_transpose(const float* __restrict__ vec) {
    __shared__ float tile[32][33];
    int k0 = blockIdx.x * 32, d0 = blockIdx.y * 32;
    int tx = threadIdx.x, ty = threadIdx.y;       // (32, 8)
    #pragma unroll
    for (int i = 0; i < 4; ++i)
        tile[ty + 8 * i][tx] = vec[(size_t)(d0 + ty + 8 * i) * KDIM + k0 + tx];
    __syncthreads();
    #pragma unroll
    for (int i = 0; i < 4; ++i) {
        int kl = ty + 8 * i;
        float v = tile[tx][kl];
        size_t o = (size_t)(k0 + kl) * DDIM + d0 + tx;
        g_vT[o]  = v;
        g_vTh[o] = __float2bfloat16_rn(v);
    }
}

// ---------------------------------------------------------------------------
// Kernel B: Phase 1 — bf16 HMMA prefilter.
//   256 thr = 8 warps (4m x 2n). CTA: 128 rows x full K; N-tiles of 128.
//   Warp tile m32 x n64 (16 mmas / k16). x resident in smem (8 padded
//   chunks of [128][40] bf16), v streamed per (tile, chunk).
// ---------------------------------------------------------------------------
#define PM   128
#define PN   128
#define PNT  (KDIM / PN)    // 32
#define PKC  32
#define NCH  (DDIM / PKC)   // 8
#define XSTR 40             // padded bf16 stride -> conflict-free frag LDS
#define SM_MMA_BYTES ((NCH * PM * XSTR + PM * XSTR) * 2)   // 92160

__global__ __launch_bounds__(256, 2) void vq_mma() {
    extern __shared__ __nv_bfloat16 smh[];
    __nv_bfloat16* xs = smh;                       // [NCH][PM][XSTR]
    __nv_bfloat16* vs = smh + NCH * PM * XSTR;     // [PM][XSTR]

    const int t    = threadIdx.x;
    const int lane = t & 31;
    const int w    = t >> 5;
    const int wm   = w & 3;            // row group: wm*32 .. +31
    const int wn   = w >> 2;           // col group: wn*64 .. +63
    const int g    = lane >> 2;
    const int tig  = lane & 3;
    const int row0 = blockIdx.x * PM;

    // ---- stage resident x tile (8 chunks, padded) ----
    {
        int r = t >> 1, hf = t & 1;
        #pragma unroll
        for (int c = 0; c < NCH; ++c) {
            const uint4* src = (const uint4*)(g_xh + (size_t)(row0 + r) * DDIM
                                              + c * PKC + hf * 16);
            uint4 v0 = src[0], v1 = src[1];
            __nv_bfloat16* dst = xs + (c * PM + r) * XSTR + hf * 16;
            *(uint4*)dst = v0;
            *(uint4*)(dst + 8) = v1;
        }
    }

    float runmin[4];
    #pragma unroll
    for (int j = 0; j < 4; ++j) runmin[j] = CUDART_INF_F;

    // prefetch v(0,0)
    uint4 pv0, pv1;
    {
        int r = t >> 1, hf = t & 1;
        const uint4* src = (const uint4*)(g_vTh + (size_t)r * DDIM + hf * 16);
        pv0 = src[0]; pv1 = src[1];
    }

    for (int nt = 0; nt < PNT; ++nt) {
        float acc[2][8][4];
        #pragma unroll
        for (int mf = 0; mf < 2; ++mf)
            #pragma unroll
            for (int nf = 0; nf < 8; ++nf)
                #pragma unroll
                for (int e = 0; e < 4; ++e) acc[mf][nf][e] = 0.0f;

        for (int c = 0; c < NCH; ++c) {
            __syncthreads();
            {
                int r = t >> 1, hf = t & 1;
                __nv_bfloat16* dst = vs + r * XSTR + hf * 16;
                *(uint4*)dst = pv0;
                *(uint4*)(dst + 8) = pv1;
            }
            __syncthreads();

            // prefetch next v chunk
            int nc = c + 1, nn = nt;
            if (nc == NCH) { nc = 0; nn = nt + 1; }
            if (nn < PNT) {
                int r = t >> 1, hf = t & 1;
                const uint4* src = (const uint4*)(g_vTh
                    + (size_t)(nn * PN + r) * DDIM + nc * PKC + hf * 16);
                pv0 = src[0]; pv1 = src[1];
            }

            const __nv_bfloat16* xc = xs + (c * PM) * XSTR;
            #pragma unroll
            for (int kh = 0; kh < 2; ++kh) {
                const int kk = kh * 16 + tig * 2;
                uint32_t a[2][4], b[8][2];
                #pragma unroll
                for (int mf = 0; mf < 2; ++mf) {
                    int r0 = wm * 32 + mf * 16 + g;
                    a[mf][0] = *(const uint32_t*)(xc + r0 * XSTR + kk);
                    a[mf][1] = *(const uint32_t*)(xc + (r0 + 8) * XSTR + kk);
                    a[mf][2] = *(const uint32_t*)(xc + r0 * XSTR + kk + 8);
                    a[mf][3] = *(const uint32_t*)(xc + (r0 + 8) * XSTR + kk + 8);
                }
                #pragma unroll
                for (int nf = 0; nf < 8; ++nf) {
                    int n0 = wn * 64 + nf * 8 + g;
                    b[nf][0] = *(const uint32_t*)(vs + n0 * XSTR + kk);
                    b[nf][1] = *(const uint32_t*)(vs + n0 * XSTR + kk + 8);
                }
                #pragma unroll
                for (int mf = 0; mf < 2; ++mf)
                    #pragma unroll
                    for (int nf = 0; nf < 8; ++nf)
                        mma_bf16(acc[mf][nf], a[mf], b[nf]);
            }
        }

        // ---- epilogue for this N-tile: running min + candidate collect ----
        const int kt0 = nt * PN + wn * 64;
        #pragma unroll
        for (int j = 0; j < 4; ++j) {
            const int mf = j >> 1, ch = (j & 1) * 2;
            const int R = row0 + wm * 32 + ((j & 1) << 3) + ((j >> 1) << 4) + g;
            float tmin = CUDART_INF_F;
            #pragma unroll
            for (int nf = 0; nf < 8; ++nf) {
                int k = kt0 + nf * 8 + tig * 2;
                float2 c2 = *(const float2*)(g_v2 + k);
                float s0 = fmaf(-2.0f, acc[mf][nf][ch + 0], c2.x);
                float s1 = fmaf(-2.0f, acc[mf][nf][ch + 1], c2.y);
                tmin = fminf(tmin, fminf(s0, s1));
            }
            // share tile-min across the 4 lanes that own this row
            tmin = fminf(tmin, __shfl_xor_sync(0xffffffffu, tmin, 1));
            tmin = fminf(tmin, __shfl_xor_sync(0xffffffffu, tmin, 2));
            runmin[j] = fminf(runmin[j], tmin);
            float thr = runmin[j] + TAU;
            #pragma unroll
            for (int nf = 0; nf < 8; ++nf) {
                int k = kt0 + nf * 8 + tig * 2;
                float2 c2 = *(const float2*)(g_v2 + k);
                float s0 = fmaf(-2.0f, acc[mf][nf][ch + 0], c2.x);
                float s1 = fmaf(-2.0f, acc[mf][nf][ch + 1], c2.y);
                if (s0 <= thr) {
                    int pos = atomicAdd(&g_candcnt[R], 1);
                    if (pos < CAP) g_cand[R * CAP + pos] = k;
                }
                if (s1 <= thr) {
                    int pos = atomicAdd(&g_candcnt[R], 1);
                    if (pos < CAP) g_cand[R * CAP + pos] = k + 1;
                }
            }
        }
    }
}

// ---------------------------------------------------------------------------
// Kernel C: Phase 2 — exact fp32 rescore of candidates (warp per row).
// ---------------------------------------------------------------------------
__global__ __launch_bounds__(256) void vq_rescore(
        const float* __restrict__ x, float* __restrict__ out_idx, int write_idx) {
    int warp = threadIdx.x >> 5;
    int lane = threadIdx.x & 31;
    int row  = blockIdx.x * 8 + warp;

    float xr[8];
    const float* xp = x + (size_t)row * DDIM;
    #pragma unroll
    for (int i = 0; i < 8; ++i) xr[i] = xp[lane + 32 * i];
    float A = g_A[row];

    int cnt = g_candcnt[row];
    float best = CUDART_INF_F;
    int   bidx = 0x7fffffff;

    int iters = (cnt <= CAP) ? cnt : KDIM;
    for (int j = 0; j < iters; ++j) {
        int k = (cnt <= CAP) ? g_cand[row * CAP + j] : j;
        const float* vp = g_vT + (size_t)k * DDIM;
        float d = 0.0f;
        #pragma unroll
        for (int i = 0; i < 8; ++i) d = fmaf(xr[i], vp[lane + 32 * i], d);
        #pragma unroll
        for (int off = 16; off > 0; off >>= 1)
            d = __fadd_rn(d, __shfl_xor_sync(0xffffffffu, d, off));
        // exact reference rounding chain (quantized at ulp ~256)
        float s = __fadd_rn(__fsub_rn(A, __fmul_rn(2.0f, d)), g_v2[k]);
        if (s < best || (s == best && k < bidx)) { best = s; bidx = k; }
    }

    if (lane == 0) {
        g_idx_buf[row] = bidx;
        if (write_idx) out_idx[row] = (float)bidx;
    }
}

// ---------------------------------------------------------------------------
// Kernel D: coalesced gather + straight-through output + loss partials
// ---------------------------------------------------------------------------
__global__ __launch_bounds__(256) void vq_gather2(const float* __restrict__ x,
                                                  float* __restrict__ out) {
    int row  = blockIdx.x * 8 + (threadIdx.x >> 5);
    int lane = threadIdx.x & 31;
    int k = g_idx_buf[row];
    const float4* q4 = (const float4*)(g_vT + (size_t)k * DDIM);
    const float4* x4 = (const float4*)(x + (size_t)row * DDIM);
    float4*       o4 = (float4*)(out + (size_t)row * DDIM);
    double acc = 0.0;
    #pragma unroll
    for (int i = 0; i < 2; ++i) {
        float4 q = q4[lane + 32 * i];
        float4 v = x4[lane + 32 * i];
        float4 o;
        o.x = __fadd_rn(v.x, __fsub_rn(q.x, v.x));
        o.y = __fadd_rn(v.y, __fsub_rn(q.y, v.y));
        o.z = __fadd_rn(v.z, __fsub_rn(q.z, v.z));
        o.w = __fadd_rn(v.w, __fsub_rn(q.w, v.w));
        o4[lane + 32 * i] = o;
        double dx = (double)v.x - (double)q.x, dy = (double)v.y - (double)q.y;
        double dz = (double)v.z - (double)q.z, dw = (double)v.w - (double)q.w;
        acc += dx * dx + dy * dy + dz * dz + dw * dw;
    }
    #pragma unroll
    for (int off = 16; off > 0; off >>= 1)
        acc += __shfl_down_sync(0xffffffffu, acc, off);
    if (lane == 0) atomicAdd(&g_partials[row & 255], acc);
}

// ---------------------------------------------------------------------------
// Kernel E: finalize losses
// ---------------------------------------------------------------------------
__global__ void vq_final(float* __restrict__ out, long long nd, int has_extra) {
    __shared__ double sd[256];
    sd[threadIdx.x] = g_partials[threadIdx.x];
    __syncthreads();
    #pragma unroll
    for (int s = 128; s > 0; s >>= 1) {
        if (threadIdx.x < s) sd[threadIdx.x] += sd[threadIdx.x + s];
        __syncthreads();
    }
    if (threadIdx.x == 0 && has_extra) {
        float l = (float)(sd[0] / (double)nd);
        out[nd]     = l;
        out[nd + 1] = l;
    }
}

// ---------------------------------------------------------------------------
extern "C" void kernel_launch(void* const* d_in, const int* in_sizes, int n_in,
                              void* d_out, int out_size) {
    const float* x   = (const float*)d_in[0];
    const float* vec = (const float*)d_in[1];
    float* out = (float*)d_out;

    int n = in_sizes[0] / DDIM;                 // 65536 rows
    long long nd = (long long)n * DDIM;
    int has_extra = ((long long)out_size >= nd + 2 + n) ? 1 : 0;

    cudaFuncSetAttribute(vq_mma, cudaFuncAttributeMaxDynamicSharedMemorySize,
                         SM_MMA_BYTES);

    vq_prep<<<(KDIM + 255) / 256, 256>>>(vec);
    vq_convx<<<(int)(((size_t)n * DDIM) / (256 * 8)), 256>>>(x);
    vq_rownorm<<<n / 8, 256>>>(x);
    vq_transpose<<<dim3(KDIM / 32, DDIM / 32), dim3(32, 8)>>>(vec);
    vq_mma<<<n / PM, 256, SM_MMA_BYTES>>>();
    vq_rescore<<<n / 8, 256>>>(x, out + nd + 2, has_extra);
    vq_gather2<<<n / 8, 256>>>(x, out);
    vq_final<<<1, 256>>>(out, nd, has_extra);
}